// round 7
// baseline (speedup 1.0000x reference)
#include <cuda_runtime.h>
#include <cuda_bf16.h>
#include <cuda_fp16.h>
#include <cuda_fp8.h>
#include <cstdint>

// ---------------- problem dims ----------------
#define MM 16384
#define DD 512
#define UU 512
#define KK 1024
#define NN 2048

// ---------------- GEMM tiling ----------------
#define BM 128
#define BN 256
#define BK 32
#define NKT (KK / BK)            // 32
#define NSTAGES 4
#define LDT 40                   // fp16 tile leading dim (halfwords): 80B rows
#define LD8 48                   // fp8 tile leading dim (bytes): 32 data + 16 pad

// ---------------- device scratch ----------------
__device__ __align__(16) __half  g_A[(size_t)MM * KK];    // fp16(a)
__device__ __align__(16) uint8_t g_Ac[(size_t)MM * KK];   // e5m2(a * 2^-12)
__device__ __align__(16) __half  g_Bhi[(size_t)NN * KK];  // fp16(b), permuted rows
__device__ __align__(16) uint8_t g_Bc[(size_t)NN * KK];   // e4m3((b - fp16(b)) * 2^12), permuted

// ---------------- prep A ----------------
__global__ void __launch_bounds__(256) prep_A_kernel(const float* __restrict__ x,
                                                     const float* __restrict__ h) {
    int gi = blockIdx.x * 256 + threadIdx.x;
    int b = gi >> 7;
    int k0 = (gi & 127) * 8;
    const float* src = (k0 < DD) ? (x + (size_t)b * DD + k0)
                                 : (h + (size_t)b * UU + (k0 - DD));
    float4 v0 = *reinterpret_cast<const float4*>(src);
    float4 v1 = *reinterpret_cast<const float4*>(src + 4);
    float v[8] = {v0.x, v0.y, v0.z, v0.w, v1.x, v1.y, v1.z, v1.w};
    __half hh[8];
    uint8_t cc[8];
#pragma unroll
    for (int j = 0; j < 8; j++) {
        hh[j] = __float2half_rn(v[j]);
        cc[j] = __nv_fp8_e5m2(v[j] * (1.0f / 4096.0f)).__x;
    }
    size_t off = (size_t)b * KK + k0;
    *reinterpret_cast<uint4*>(&g_A[off]) = *reinterpret_cast<uint4*>(hh);
    *reinterpret_cast<uint2*>(&g_Ac[off]) = *reinterpret_cast<uint2*>(cc);
}

// ---------------- prep B: transpose + permute (p = u*4 + gate) ----------------
__global__ void prep_B_kernel(const float* __restrict__ Wk, const float* __restrict__ Wr) {
    __shared__ float t[32][33];
    int n0 = blockIdx.x * 32, k0 = blockIdx.y * 32;
    int tn = threadIdx.x, tk = threadIdx.y;  // block (32, 8)
#pragma unroll
    for (int j = 0; j < 32; j += 8) {
        int k = k0 + tk + j;
        float v = (k < DD) ? Wk[(size_t)k * NN + n0 + tn]
                           : Wr[(size_t)(k - DD) * NN + n0 + tn];
        t[tk + j][tn] = v;
    }
    __syncthreads();
#pragma unroll
    for (int j = 0; j < 32; j += 8) {
        int n = n0 + tk + j;
        int k = k0 + tn;
        int p = ((n & 511) << 2) + (n >> 9);  // unit*4 + gate
        float v = t[tn][tk + j];
        __half hv = __float2half_rn(v);
        float blo = v - __half2float(hv);
        g_Bhi[(size_t)p * KK + k] = hv;
        g_Bc[(size_t)p * KK + k] = __nv_fp8_e4m3(blo * 4096.0f).__x;
    }
}

// ---------------- fused GEMM (f16 main + fp8 correction) + gates ----------------
struct Stage {
    __half  A[BM * LDT];     // 10240 B
    __half  Bhi[BN * LDT];   // 20480 B
    uint8_t Ac[BM * LD8];    // 6144 B
    uint8_t Bc[BN * LD8];    // 12288 B
};  // 49152 B

__device__ __forceinline__ void cp_async16(void* dst, const void* src) {
    unsigned d = (unsigned)__cvta_generic_to_shared(dst);
    asm volatile("cp.async.cg.shared.global [%0], [%1], 16;" :: "r"(d), "l"(src) : "memory");
}

__device__ __forceinline__ void ldsm_x4(unsigned r[4], uint32_t addr) {
    asm volatile("ldmatrix.sync.aligned.m8n8.x4.shared.b16 {%0,%1,%2,%3}, [%4];"
                 : "=r"(r[0]), "=r"(r[1]), "=r"(r[2]), "=r"(r[3]) : "r"(addr));
}

__device__ __forceinline__ void mma_f16(float c[4], const unsigned a[4],
                                        unsigned b0, unsigned b1) {
    asm volatile(
        "mma.sync.aligned.m16n8k16.row.col.f32.f16.f16.f32 "
        "{%0,%1,%2,%3}, {%4,%5,%6,%7}, {%8,%9}, {%0,%1,%2,%3};"
        : "+f"(c[0]), "+f"(c[1]), "+f"(c[2]), "+f"(c[3])
        : "r"(a[0]), "r"(a[1]), "r"(a[2]), "r"(a[3]), "r"(b0), "r"(b1));
}

__device__ __forceinline__ void mma_fp8(float c[4], const unsigned a[4],
                                        unsigned b0, unsigned b1) {
    asm volatile(
        "mma.sync.aligned.m16n8k32.row.col.f32.e5m2.e4m3.f32 "
        "{%0,%1,%2,%3}, {%4,%5,%6,%7}, {%8,%9}, {%0,%1,%2,%3};"
        : "+f"(c[0]), "+f"(c[1]), "+f"(c[2]), "+f"(c[3])
        : "r"(a[0]), "r"(a[1]), "r"(a[2]), "r"(a[3]), "r"(b0), "r"(b1));
}

__device__ __forceinline__ float sigf(float x) { return 1.0f / (1.0f + __expf(-x)); }

#define LDZ 260  // padded z stride in floats

__global__ void __launch_bounds__(512)
lstm_gemm_kernel(const float* __restrict__ c_tm1,
                 const float* __restrict__ pw,
                 const float* __restrict__ bias,
                 float* __restrict__ out) {
    extern __shared__ __align__(16) unsigned char smem_raw[];
    Stage* stages = reinterpret_cast<Stage*>(smem_raw);

    const int tid = threadIdx.x;
    const int lane = tid & 31;
    const int wid = tid >> 5;        // 0..15
    const int mw = (wid >> 2) * 32;  // 4 warps in M
    const int nw = (wid & 3) * 64;   // 4 warps in N
    const int m0 = blockIdx.y * BM;
    const int n0 = blockIdx.x * BN;
    const int r = lane >> 2, q = lane & 3;

    const int lrow = (lane & 7) + ((lane >> 3) & 1) * 8;
    const int lkof = (lane >> 4) * 16;  // bytes

    auto load_stage = [&](int s, int kt) {
        Stage* st = &stages[s];
        int k0 = kt * BK;
        {   // A fp16: 512 chunks, 1/thread
            int row = tid >> 2, seg = tid & 3;
            cp_async16(&st->A[row * LDT + seg * 8],
                       &g_A[(size_t)(m0 + row) * KK + k0 + seg * 8]);
        }
#pragma unroll
        for (int i = 0; i < 2; i++) {  // Bhi fp16: 1024 chunks, 2/thread
            int c = tid + i * 512;
            int row = c >> 2, seg = c & 3;
            cp_async16(&st->Bhi[row * LDT + seg * 8],
                       &g_Bhi[(size_t)(n0 + row) * KK + k0 + seg * 8]);
        }
        {   // Bc fp8: 512 chunks, 1/thread
            int row = tid >> 1, seg = tid & 1;
            cp_async16(&st->Bc[row * LD8 + seg * 16],
                       &g_Bc[(size_t)(n0 + row) * KK + k0 + seg * 16]);
        }
        if (tid < 256) {  // Ac fp8: 256 chunks
            int row = tid >> 1, seg = tid & 1;
            cp_async16(&st->Ac[row * LD8 + seg * 16],
                       &g_Ac[(size_t)(m0 + row) * KK + k0 + seg * 16]);
        }
        asm volatile("cp.async.commit_group;" ::: "memory");
    };

    float acc[2][8][4];
#pragma unroll
    for (int a = 0; a < 2; a++)
#pragma unroll
        for (int b = 0; b < 8; b++)
#pragma unroll
            for (int c = 0; c < 4; c++) acc[a][b][c] = 0.0f;

#pragma unroll
    for (int s = 0; s < NSTAGES - 1; s++) load_stage(s, s);

    for (int kt = 0; kt < NKT; kt++) {
        asm volatile("cp.async.wait_group %0;" :: "n"(NSTAGES - 2) : "memory");
        __syncthreads();
        if (kt + NSTAGES - 1 < NKT)
            load_stage((kt + NSTAGES - 1) % NSTAGES, kt + NSTAGES - 1);
        else
            asm volatile("cp.async.commit_group;" ::: "memory");

        const Stage* st = &stages[kt % NSTAGES];

        // ---- main f16 pass: two k16 halves ----
#pragma unroll
        for (int kk = 0; kk < BK; kk += 16) {
            unsigned ah[2][4];
#pragma unroll
            for (int ms = 0; ms < 2; ms++) {
                uint32_t boff = (uint32_t)(((mw + ms * 16 + lrow) * LDT + kk) * 2 + lkof);
                ldsm_x4(ah[ms], (unsigned)__cvta_generic_to_shared(
                                    (const char*)st->A + boff));
            }
#pragma unroll
            for (int p = 0; p < 4; p++) {
                uint32_t boff = (uint32_t)(((nw + p * 16 + lrow) * LDT + kk) * 2 + lkof);
                unsigned bh[4];
                ldsm_x4(bh, (unsigned)__cvta_generic_to_shared(
                                (const char*)st->Bhi + boff));
#pragma unroll
                for (int e = 0; e < 2; e++)
#pragma unroll
                    for (int ms = 0; ms < 2; ms++)
                        mma_f16(acc[ms][p * 2 + e], ah[ms], bh[e], bh[e + 2]);
            }
        }

        // ---- correction fp8 pass: one k32 step (scales cancel: 2^-12 * 2^12) ----
        {
            unsigned ac[2][4];
#pragma unroll
            for (int ms = 0; ms < 2; ms++) {
                const uint8_t* base = st->Ac + (mw + ms * 16 + r) * LD8 + q * 4;
                ac[ms][0] = *reinterpret_cast<const unsigned*>(base);
                ac[ms][1] = *reinterpret_cast<const unsigned*>(base + 8 * LD8);
                ac[ms][2] = *reinterpret_cast<const unsigned*>(base + 16);
                ac[ms][3] = *reinterpret_cast<const unsigned*>(base + 8 * LD8 + 16);
            }
#pragma unroll
            for (int sl = 0; sl < 8; sl++) {
                const uint8_t* base = st->Bc + (nw + sl * 8 + r) * LD8 + q * 4;
                unsigned b0 = *reinterpret_cast<const unsigned*>(base);
                unsigned b1 = *reinterpret_cast<const unsigned*>(base + 16);
#pragma unroll
                for (int ms = 0; ms < 2; ms++)
                    mma_fp8(acc[ms][sl], ac[ms], b0, b1);
            }
        }
    }

    // ---------------- fused gate epilogue ----------------
    __syncthreads();
    float* zsm = reinterpret_cast<float*>(smem_raw);  // [128][LDZ]

#pragma unroll
    for (int ms = 0; ms < 2; ms++)
#pragma unroll
        for (int ns = 0; ns < 8; ns++) {
            int row = mw + ms * 16 + r;
            int col = nw + ns * 8 + 2 * q;
            *(float2*)&zsm[row * LDZ + col] = make_float2(acc[ms][ns][0], acc[ms][ns][1]);
            *(float2*)&zsm[(row + 8) * LDZ + col] = make_float2(acc[ms][ns][2], acc[ms][ns][3]);
        }
    __syncthreads();

    {
        const int ul = tid & 63;             // local unit 0..63
        const int u = blockIdx.x * 64 + ul;  // global unit
        const float bi = bias[u];
        const float bf = bias[512 + u];
        const float bg = bias[1024 + u];
        const float bo = bias[1536 + u];
        const float pwi = pw[u * 3 + 0];
        const float pwf = pw[u * 3 + 1];
        const float pwo = pw[u * 3 + 2];
#pragma unroll
        for (int it = 0; it < 16; it++) {
            int row = (tid >> 6) * 16 + it;
            int m = m0 + row;
            float4 zz = *reinterpret_cast<const float4*>(&zsm[row * LDZ + ul * 4]);
            float cprev = c_tm1[(size_t)m * UU + u];
            float iv = sigf(zz.x + bi + cprev * pwi);
            float fv = sigf(zz.y + bf + cprev * pwf);
            float gv = tanhf(zz.z + bg);
            float cc = fv * cprev + iv * gv;
            float ov = sigf(zz.w + bo + cc * pwo);
            out[(size_t)m * UU + u] = ov * tanhf(cc);
            out[(size_t)MM * UU + (size_t)m * UU + u] = cc;
        }
    }
}

// ---------------- launch ----------------
extern "C" void kernel_launch(void* const* d_in, const int* in_sizes, int n_in,
                              void* d_out, int out_size) {
    const float* x    = (const float*)d_in[0];
    const float* h    = (const float*)d_in[1];
    const float* c    = (const float*)d_in[2];
    const float* Wk   = (const float*)d_in[3];
    const float* Wr   = (const float*)d_in[4];
    const float* pw   = (const float*)d_in[5];
    const float* bias = (const float*)d_in[6];
    float* out = (float*)d_out;

    cudaFuncSetAttribute(lstm_gemm_kernel, cudaFuncAttributeMaxDynamicSharedMemorySize,
                         (int)(NSTAGES * sizeof(Stage)));

    prep_A_kernel<<<(MM * KK / 8) / 256, 256>>>(x, h);
    prep_B_kernel<<<dim3(NN / 32, KK / 32), dim3(32, 8)>>>(Wk, Wr);
    lstm_gemm_kernel<<<dim3(NN / BN, MM / BM), 512, NSTAGES * sizeof(Stage)>>>(c, pw, bias, out);
}

// round 8
// speedup vs baseline: 1.5982x; 1.5982x over previous
#include <cuda_runtime.h>
#include <cuda_bf16.h>
#include <cuda_fp16.h>
#include <cstdint>

// ---------------- problem dims ----------------
#define MM 16384
#define DD 512
#define UU 512
#define KK 1024
#define NN 2048

// ---------------- GEMM tiling ----------------
#define BM 128
#define BN 256
#define BK 32
#define NKT (KK / BK)            // 32
#define NSTAGES 6
#define LDT 40                   // fp16 tile leading dim (halfwords): 80B rows

// ---------------- device scratch ----------------
__device__ __align__(16) __half g_A[(size_t)MM * KK];    // fp16(a)
__device__ __align__(16) __half g_Bhi[(size_t)NN * KK];  // fp16(b), permuted rows

// ---------------- prep A ----------------
__global__ void __launch_bounds__(256) prep_A_kernel(const float* __restrict__ x,
                                                     const float* __restrict__ h) {
    int gi = blockIdx.x * 256 + threadIdx.x;
    int b = gi >> 7;
    int k0 = (gi & 127) * 8;
    const float* src = (k0 < DD) ? (x + (size_t)b * DD + k0)
                                 : (h + (size_t)b * UU + (k0 - DD));
    float4 v0 = *reinterpret_cast<const float4*>(src);
    float4 v1 = *reinterpret_cast<const float4*>(src + 4);
    float v[8] = {v0.x, v0.y, v0.z, v0.w, v1.x, v1.y, v1.z, v1.w};
    __half hh[8];
#pragma unroll
    for (int j = 0; j < 8; j++) hh[j] = __float2half_rn(v[j]);
    *reinterpret_cast<uint4*>(&g_A[(size_t)b * KK + k0]) = *reinterpret_cast<uint4*>(hh);
}

// ---------------- prep B: transpose + permute (p = u*4 + gate) ----------------
__global__ void prep_B_kernel(const float* __restrict__ Wk, const float* __restrict__ Wr) {
    __shared__ float t[32][33];
    int n0 = blockIdx.x * 32, k0 = blockIdx.y * 32;
    int tn = threadIdx.x, tk = threadIdx.y;  // block (32, 8)
#pragma unroll
    for (int j = 0; j < 32; j += 8) {
        int k = k0 + tk + j;
        float v = (k < DD) ? Wk[(size_t)k * NN + n0 + tn]
                           : Wr[(size_t)(k - DD) * NN + n0 + tn];
        t[tk + j][tn] = v;
    }
    __syncthreads();
#pragma unroll
    for (int j = 0; j < 32; j += 8) {
        int n = n0 + tk + j;
        int k = k0 + tn;
        int p = ((n & 511) << 2) + (n >> 9);  // unit*4 + gate
        g_Bhi[(size_t)p * KK + k] = __float2half_rn(t[tn][tk + j]);
    }
}

// ---------------- fused GEMM (single-pass f16 mma.sync) + gates ----------------
struct Stage {
    __half A[BM * LDT];     // 10240 B
    __half Bhi[BN * LDT];   // 20480 B
};  // 30720 B

__device__ __forceinline__ void cp_async16(void* dst, const void* src) {
    unsigned d = (unsigned)__cvta_generic_to_shared(dst);
    asm volatile("cp.async.cg.shared.global [%0], [%1], 16;" :: "r"(d), "l"(src) : "memory");
}

__device__ __forceinline__ void ldsm_x4(unsigned r[4], uint32_t addr) {
    asm volatile("ldmatrix.sync.aligned.m8n8.x4.shared.b16 {%0,%1,%2,%3}, [%4];"
                 : "=r"(r[0]), "=r"(r[1]), "=r"(r[2]), "=r"(r[3]) : "r"(addr));
}

__device__ __forceinline__ void mma_f16(float c[4], const unsigned a[4],
                                        unsigned b0, unsigned b1) {
    asm volatile(
        "mma.sync.aligned.m16n8k16.row.col.f32.f16.f16.f32 "
        "{%0,%1,%2,%3}, {%4,%5,%6,%7}, {%8,%9}, {%0,%1,%2,%3};"
        : "+f"(c[0]), "+f"(c[1]), "+f"(c[2]), "+f"(c[3])
        : "r"(a[0]), "r"(a[1]), "r"(a[2]), "r"(a[3]), "r"(b0), "r"(b1));
}

__device__ __forceinline__ float sigf(float x) { return 1.0f / (1.0f + __expf(-x)); }

#define LDZ 260  // padded z stride in floats

__global__ void __launch_bounds__(512)
lstm_gemm_kernel(const float* __restrict__ c_tm1,
                 const float* __restrict__ pw,
                 const float* __restrict__ bias,
                 float* __restrict__ out) {
    extern __shared__ __align__(16) unsigned char smem_raw[];
    Stage* stages = reinterpret_cast<Stage*>(smem_raw);

    const int tid = threadIdx.x;
    const int lane = tid & 31;
    const int wid = tid >> 5;        // 0..15
    const int mw = (wid >> 2) * 32;  // 4 warps in M
    const int nw = (wid & 3) * 64;   // 4 warps in N
    const int m0 = blockIdx.y * BM;
    const int n0 = blockIdx.x * BN;
    const int r = lane >> 2, q = lane & 3;

    const int lrow = (lane & 7) + ((lane >> 3) & 1) * 8;
    const int lkof = (lane >> 4) * 16;  // bytes

    auto load_stage = [&](int s, int kt) {
        Stage* st = &stages[s];
        int k0 = kt * BK;
        {   // A: 512 16B-chunks, 1/thread
            int row = tid >> 2, seg = tid & 3;
            cp_async16(&st->A[row * LDT + seg * 8],
                       &g_A[(size_t)(m0 + row) * KK + k0 + seg * 8]);
        }
#pragma unroll
        for (int i = 0; i < 2; i++) {  // Bhi: 1024 chunks, 2/thread
            int c = tid + i * 512;
            int row = c >> 2, seg = c & 3;
            cp_async16(&st->Bhi[row * LDT + seg * 8],
                       &g_Bhi[(size_t)(n0 + row) * KK + k0 + seg * 8]);
        }
        asm volatile("cp.async.commit_group;" ::: "memory");
    };

    float acc[2][8][4];
#pragma unroll
    for (int a = 0; a < 2; a++)
#pragma unroll
        for (int b = 0; b < 8; b++)
#pragma unroll
            for (int c = 0; c < 4; c++) acc[a][b][c] = 0.0f;

#pragma unroll
    for (int s = 0; s < NSTAGES - 1; s++) load_stage(s, s);

    for (int kt = 0; kt < NKT; kt++) {
        asm volatile("cp.async.wait_group %0;" :: "n"(NSTAGES - 2) : "memory");
        __syncthreads();
        if (kt + NSTAGES - 1 < NKT)
            load_stage((kt + NSTAGES - 1) % NSTAGES, kt + NSTAGES - 1);
        else
            asm volatile("cp.async.commit_group;" ::: "memory");

        const Stage* st = &stages[kt % NSTAGES];
#pragma unroll
        for (int kk = 0; kk < BK; kk += 16) {
            unsigned ah[2][4];
#pragma unroll
            for (int ms = 0; ms < 2; ms++) {
                uint32_t boff = (uint32_t)(((mw + ms * 16 + lrow) * LDT + kk) * 2 + lkof);
                ldsm_x4(ah[ms], (unsigned)__cvta_generic_to_shared(
                                    (const char*)st->A + boff));
            }
#pragma unroll
            for (int p = 0; p < 4; p++) {
                uint32_t boff = (uint32_t)(((nw + p * 16 + lrow) * LDT + kk) * 2 + lkof);
                unsigned bh[4];
                ldsm_x4(bh, (unsigned)__cvta_generic_to_shared(
                                (const char*)st->Bhi + boff));
#pragma unroll
                for (int e = 0; e < 2; e++)
#pragma unroll
                    for (int ms = 0; ms < 2; ms++)
                        mma_f16(acc[ms][p * 2 + e], ah[ms], bh[e], bh[e + 2]);
            }
        }
    }

    // ---------------- fused gate epilogue ----------------
    __syncthreads();
    float* zsm = reinterpret_cast<float*>(smem_raw);  // [128][LDZ]

#pragma unroll
    for (int ms = 0; ms < 2; ms++)
#pragma unroll
        for (int ns = 0; ns < 8; ns++) {
            int row = mw + ms * 16 + r;
            int col = nw + ns * 8 + 2 * q;
            *(float2*)&zsm[row * LDZ + col] = make_float2(acc[ms][ns][0], acc[ms][ns][1]);
            *(float2*)&zsm[(row + 8) * LDZ + col] = make_float2(acc[ms][ns][2], acc[ms][ns][3]);
        }
    __syncthreads();

    {
        const int ul = tid & 63;             // local unit 0..63
        const int u = blockIdx.x * 64 + ul;  // global unit
        const float bi = bias[u];
        const float bf = bias[512 + u];
        const float bg = bias[1024 + u];
        const float bo = bias[1536 + u];
        const float pwi = pw[u * 3 + 0];
        const float pwf = pw[u * 3 + 1];
        const float pwo = pw[u * 3 + 2];
#pragma unroll
        for (int it = 0; it < 16; it++) {
            int row = (tid >> 6) * 16 + it;
            int m = m0 + row;
            float4 zz = *reinterpret_cast<const float4*>(&zsm[row * LDZ + ul * 4]);
            float cprev = c_tm1[(size_t)m * UU + u];
            float iv = sigf(zz.x + bi + cprev * pwi);
            float fv = sigf(zz.y + bf + cprev * pwf);
            float gv = tanhf(zz.z + bg);
            float cc = fv * cprev + iv * gv;
            float ov = sigf(zz.w + bo + cc * pwo);
            out[(size_t)m * UU + u] = ov * tanhf(cc);
            out[(size_t)MM * UU + (size_t)m * UU + u] = cc;
        }
    }
}

// ---------------- launch ----------------
extern "C" void kernel_launch(void* const* d_in, const int* in_sizes, int n_in,
                              void* d_out, int out_size) {
    const float* x    = (const float*)d_in[0];
    const float* h    = (const float*)d_in[1];
    const float* c    = (const float*)d_in[2];
    const float* Wk   = (const float*)d_in[3];
    const float* Wr   = (const float*)d_in[4];
    const float* pw   = (const float*)d_in[5];
    const float* bias = (const float*)d_in[6];
    float* out = (float*)d_out;

    cudaFuncSetAttribute(lstm_gemm_kernel, cudaFuncAttributeMaxDynamicSharedMemorySize,
                         (int)(NSTAGES * sizeof(Stage)));

    prep_A_kernel<<<(MM * KK / 8) / 256, 256>>>(x, h);
    prep_B_kernel<<<dim3(NN / 32, KK / 32), dim3(32, 8)>>>(Wk, Wr);
    lstm_gemm_kernel<<<dim3(NN / BN, MM / BM), 512, NSTAGES * sizeof(Stage)>>>(c, pw, bias, out);
}

// round 9
// speedup vs baseline: 1.7936x; 1.1223x over previous
#include <cuda_runtime.h>
#include <cuda_bf16.h>
#include <cuda_fp16.h>
#include <cstdint>

// ---------------- problem dims ----------------
#define MM 16384
#define DD 512
#define UU 512
#define KK 1024
#define NN 2048

// ---------------- GEMM tiling ----------------
#define BM 128
#define BN 128
#define BK 32
#define NKT (KK / BK)            // 32
#define NSTAGES 5
#define LDT 40                   // fp16 tile leading dim (halfwords): 80B rows

// ---------------- device scratch ----------------
__device__ __align__(16) __half g_A[(size_t)MM * KK];    // fp16(a)
__device__ __align__(16) __half g_Bhi[(size_t)NN * KK];  // fp16(b), permuted rows

// ---------------- prep A ----------------
__global__ void __launch_bounds__(256) prep_A_kernel(const float* __restrict__ x,
                                                     const float* __restrict__ h) {
    int gi = blockIdx.x * 256 + threadIdx.x;
    int b = gi >> 7;
    int k0 = (gi & 127) * 8;
    const float* src = (k0 < DD) ? (x + (size_t)b * DD + k0)
                                 : (h + (size_t)b * UU + (k0 - DD));
    float4 v0 = *reinterpret_cast<const float4*>(src);
    float4 v1 = *reinterpret_cast<const float4*>(src + 4);
    float v[8] = {v0.x, v0.y, v0.z, v0.w, v1.x, v1.y, v1.z, v1.w};
    __half hh[8];
#pragma unroll
    for (int j = 0; j < 8; j++) hh[j] = __float2half_rn(v[j]);
    *reinterpret_cast<uint4*>(&g_A[(size_t)b * KK + k0]) = *reinterpret_cast<uint4*>(hh);
}

// ---------------- prep B: transpose + permute (p = u*4 + gate) ----------------
__global__ void prep_B_kernel(const float* __restrict__ Wk, const float* __restrict__ Wr) {
    __shared__ float t[32][33];
    int n0 = blockIdx.x * 32, k0 = blockIdx.y * 32;
    int tn = threadIdx.x, tk = threadIdx.y;  // block (32, 8)
#pragma unroll
    for (int j = 0; j < 32; j += 8) {
        int k = k0 + tk + j;
        float v = (k < DD) ? Wk[(size_t)k * NN + n0 + tn]
                           : Wr[(size_t)(k - DD) * NN + n0 + tn];
        t[tk + j][tn] = v;
    }
    __syncthreads();
#pragma unroll
    for (int j = 0; j < 32; j += 8) {
        int n = n0 + tk + j;
        int k = k0 + tn;
        int p = ((n & 511) << 2) + (n >> 9);  // unit*4 + gate
        g_Bhi[(size_t)p * KK + k] = __float2half_rn(t[tn][tk + j]);
    }
}

// ---------------- fused GEMM (single-pass f16, 2 CTAs/SM) + gates ----------------
struct Stage {
    __half A[BM * LDT];     // 10240 B
    __half Bhi[BN * LDT];   // 10240 B
};  // 20480 B

__device__ __forceinline__ void cp_async16(void* dst, const void* src) {
    unsigned d = (unsigned)__cvta_generic_to_shared(dst);
    asm volatile("cp.async.cg.shared.global [%0], [%1], 16;" :: "r"(d), "l"(src) : "memory");
}

__device__ __forceinline__ void ldsm_x4(unsigned r[4], uint32_t addr) {
    asm volatile("ldmatrix.sync.aligned.m8n8.x4.shared.b16 {%0,%1,%2,%3}, [%4];"
                 : "=r"(r[0]), "=r"(r[1]), "=r"(r[2]), "=r"(r[3]) : "r"(addr));
}

__device__ __forceinline__ void mma_f16(float c[4], const unsigned a[4],
                                        unsigned b0, unsigned b1) {
    asm volatile(
        "mma.sync.aligned.m16n8k16.row.col.f32.f16.f16.f32 "
        "{%0,%1,%2,%3}, {%4,%5,%6,%7}, {%8,%9}, {%0,%1,%2,%3};"
        : "+f"(c[0]), "+f"(c[1]), "+f"(c[2]), "+f"(c[3])
        : "r"(a[0]), "r"(a[1]), "r"(a[2]), "r"(a[3]), "r"(b0), "r"(b1));
}

__device__ __forceinline__ float sigf(float x) { return 1.0f / (1.0f + __expf(-x)); }

#define LDZ 132  // padded z stride in floats

__global__ void __launch_bounds__(256, 2)
lstm_gemm_kernel(const float* __restrict__ c_tm1,
                 const float* __restrict__ pw,
                 const float* __restrict__ bias,
                 float* __restrict__ out) {
    extern __shared__ __align__(16) unsigned char smem_raw[];
    Stage* stages = reinterpret_cast<Stage*>(smem_raw);

    const int tid = threadIdx.x;
    const int lane = tid & 31;
    const int wid = tid >> 5;        // 0..7
    const int mw = (wid >> 1) * 32;  // 4 warps in M
    const int nw = (wid & 1) * 64;   // 2 warps in N
    const int m0 = blockIdx.y * BM;
    const int n0 = blockIdx.x * BN;
    const int r = lane >> 2, q = lane & 3;

    const int lrow = (lane & 7) + ((lane >> 3) & 1) * 8;
    const int lkof = (lane >> 4) * 16;  // bytes

    auto load_stage = [&](int s, int kt) {
        Stage* st = &stages[s];
        int k0 = kt * BK;
        {   // A: 512 16B-chunks, 2/thread
#pragma unroll
            for (int i = 0; i < 2; i++) {
                int c = tid + i * 256;
                int row = c >> 2, seg = c & 3;
                cp_async16(&st->A[row * LDT + seg * 8],
                           &g_A[(size_t)(m0 + row) * KK + k0 + seg * 8]);
            }
        }
        {   // B: 512 chunks, 2/thread
#pragma unroll
            for (int i = 0; i < 2; i++) {
                int c = tid + i * 256;
                int row = c >> 2, seg = c & 3;
                cp_async16(&st->Bhi[row * LDT + seg * 8],
                           &g_Bhi[(size_t)(n0 + row) * KK + k0 + seg * 8]);
            }
        }
        asm volatile("cp.async.commit_group;" ::: "memory");
    };

    float acc[2][8][4];
#pragma unroll
    for (int a = 0; a < 2; a++)
#pragma unroll
        for (int b = 0; b < 8; b++)
#pragma unroll
            for (int c = 0; c < 4; c++) acc[a][b][c] = 0.0f;

#pragma unroll
    for (int s = 0; s < NSTAGES - 1; s++) load_stage(s, s);

    for (int kt = 0; kt < NKT; kt++) {
        asm volatile("cp.async.wait_group %0;" :: "n"(NSTAGES - 2) : "memory");
        __syncthreads();
        if (kt + NSTAGES - 1 < NKT)
            load_stage((kt + NSTAGES - 1) % NSTAGES, kt + NSTAGES - 1);
        else
            asm volatile("cp.async.commit_group;" ::: "memory");

        const Stage* st = &stages[kt % NSTAGES];
#pragma unroll
        for (int kk = 0; kk < BK; kk += 16) {
            unsigned ah[2][4];
#pragma unroll
            for (int ms = 0; ms < 2; ms++) {
                uint32_t boff = (uint32_t)(((mw + ms * 16 + lrow) * LDT + kk) * 2 + lkof);
                ldsm_x4(ah[ms], (unsigned)__cvta_generic_to_shared(
                                    (const char*)st->A + boff));
            }
#pragma unroll
            for (int p = 0; p < 4; p++) {
                uint32_t boff = (uint32_t)(((nw + p * 16 + lrow) * LDT + kk) * 2 + lkof);
                unsigned bh[4];
                ldsm_x4(bh, (unsigned)__cvta_generic_to_shared(
                                (const char*)st->Bhi + boff));
#pragma unroll
                for (int e = 0; e < 2; e++)
#pragma unroll
                    for (int ms = 0; ms < 2; ms++)
                        mma_f16(acc[ms][p * 2 + e], ah[ms], bh[e], bh[e + 2]);
            }
        }
    }

    // ---------------- fused gate epilogue ----------------
    __syncthreads();
    float* zsm = reinterpret_cast<float*>(smem_raw);  // [128][LDZ]

#pragma unroll
    for (int ms = 0; ms < 2; ms++)
#pragma unroll
        for (int ns = 0; ns < 8; ns++) {
            int row = mw + ms * 16 + r;
            int col = nw + ns * 8 + 2 * q;
            *(float2*)&zsm[row * LDZ + col] = make_float2(acc[ms][ns][0], acc[ms][ns][1]);
            *(float2*)&zsm[(row + 8) * LDZ + col] = make_float2(acc[ms][ns][2], acc[ms][ns][3]);
        }
    __syncthreads();

    {
        const int ul = tid & 31;             // local unit 0..31
        const int u = blockIdx.x * 32 + ul;  // global unit
        const float bi = bias[u];
        const float bf = bias[512 + u];
        const float bg = bias[1024 + u];
        const float bo = bias[1536 + u];
        const float pwi = pw[u * 3 + 0];
        const float pwf = pw[u * 3 + 1];
        const float pwo = pw[u * 3 + 2];
#pragma unroll
        for (int it = 0; it < 16; it++) {
            int row = (tid >> 5) * 16 + it;
            int m = m0 + row;
            float4 zz = *reinterpret_cast<const float4*>(&zsm[row * LDZ + ul * 4]);
            float cprev = c_tm1[(size_t)m * UU + u];
            float iv = sigf(zz.x + bi + cprev * pwi);
            float fv = sigf(zz.y + bf + cprev * pwf);
            float gv = tanhf(zz.z + bg);
            float cc = fv * cprev + iv * gv;
            float ov = sigf(zz.w + bo + cc * pwo);
            out[(size_t)m * UU + u] = ov * tanhf(cc);
            out[(size_t)MM * UU + (size_t)m * UU + u] = cc;
        }
    }
}

// ---------------- launch ----------------
extern "C" void kernel_launch(void* const* d_in, const int* in_sizes, int n_in,
                              void* d_out, int out_size) {
    const float* x    = (const float*)d_in[0];
    const float* h    = (const float*)d_in[1];
    const float* c    = (const float*)d_in[2];
    const float* Wk   = (const float*)d_in[3];
    const float* Wr   = (const float*)d_in[4];
    const float* pw   = (const float*)d_in[5];
    const float* bias = (const float*)d_in[6];
    float* out = (float*)d_out;

    cudaFuncSetAttribute(lstm_gemm_kernel, cudaFuncAttributeMaxDynamicSharedMemorySize,
                         (int)(NSTAGES * sizeof(Stage)));

    prep_A_kernel<<<(MM * KK / 8) / 256, 256>>>(x, h);
    prep_B_kernel<<<dim3(NN / 32, KK / 32), dim3(32, 8)>>>(Wk, Wr);
    lstm_gemm_kernel<<<dim3(NN / BN, MM / BM), 256, NSTAGES * sizeof(Stage)>>>(c, pw, bias, out);
}